// round 10
// baseline (speedup 1.0000x reference)
#include <cuda_runtime.h>
#include <cuda_bf16.h>

// char_feats: [L=512, B=256, D=256] f32 (time-major)
// word_ids:   [B, L] i32 (per-row non-decreasing, dense 0..n-1, < 128)
// attention_mask: [B, L] i32
// out: word_feats [W=128, B, D] f32 (+ masks [W, B] f32 if out_size allows)
#define LSEQ 512
#define NW   128
#define BATCH 256
#define DDIM  256
#define WPB   4            // words per block

__device__ __forceinline__ int clampw(int v) {
    return v < 0 ? 0 : (v > NW - 1 ? NW - 1 : v);
}

// 4/2/1 ladder; single accumulator; evict-first streaming loads.
__device__ __forceinline__ float4 pool_body(const float4* p, int stride4, int n) {
    float4 acc = make_float4(0.f, 0.f, 0.f, 0.f);
    int rem = n;
    while (rem >= 4) {
        float4 v0 = __ldcs(p);
        float4 v1 = __ldcs(p + stride4);
        float4 v2 = __ldcs(p + 2 * stride4);
        float4 v3 = __ldcs(p + 3 * stride4);
        acc.x += v0.x; acc.y += v0.y; acc.z += v0.z; acc.w += v0.w;
        acc.x += v1.x; acc.y += v1.y; acc.z += v1.z; acc.w += v1.w;
        acc.x += v2.x; acc.y += v2.y; acc.z += v2.z; acc.w += v2.w;
        acc.x += v3.x; acc.y += v3.y; acc.z += v3.z; acc.w += v3.w;
        p += 4 * stride4;
        rem -= 4;
    }
    if (rem >= 2) {
        float4 v0 = __ldcs(p);
        float4 v1 = __ldcs(p + stride4);
        acc.x += v0.x; acc.y += v0.y; acc.z += v0.z; acc.w += v0.w;
        acc.x += v1.x; acc.y += v1.y; acc.z += v1.z; acc.w += v1.w;
        p += 2 * stride4;
        rem -= 2;
    }
    if (rem >= 1) {
        float4 v0 = __ldcs(p);
        acc.x += v0.x; acc.y += v0.y; acc.z += v0.z; acc.w += v0.w;
    }
    return acc;
}

// One block per (4 words, batch); b fast axis. One metadata pass yields the
// 5 cut points c[j] = #(id < wbase+j); word j pools rows [c[j], c[j+1]) ∩
// [1, hi). The 4 words' ranges are contiguous -> block streams one segment.
__global__ void __launch_bounds__(64, 32)
fused_kernel(const float* __restrict__ cf,
             const int* __restrict__ word_ids,
             const int* __restrict__ amask,
             float* __restrict__ out,
             float* __restrict__ mask_out) {
    int lid = blockIdx.x;
    int b = lid & (BATCH - 1);        // fast axis
    int wbase = (lid >> 8) * WPB;     // slow axis: words wbase..wbase+3
    int t = threadIdx.x;              // 0..63

    __shared__ int sred[4];           // two packed partials x 2 warps
    __shared__ int scut[WPB + 1];
    __shared__ int smeta[2];          // hi, wordnum

    // --- metadata: 2KB id row + 2KB mask row, cooperative ---
    const int4* wp = reinterpret_cast<const int4*>(word_ids + b * LSEQ);
    int4 w0 = __ldg(wp + 2 * t);
    int4 w1 = __ldg(wp + 2 * t + 1);
    const int4* mp = reinterpret_cast<const int4*>(amask + b * LSEQ);
    int4 m0 = __ldg(mp + 2 * t);
    int4 m1 = __ldg(mp + 2 * t + 1);

    int ids[8] = { clampw(w0.x), clampw(w0.y), clampw(w0.z), clampw(w0.w),
                   clampw(w1.x), clampw(w1.y), clampw(w1.z), clampw(w1.w) };

    int c0 = 0, c1 = 0, c2 = 0, c3 = 0, c4 = 0;
    #pragma unroll
    for (int i = 0; i < 8; ++i) {
        int d = ids[i] - wbase;       // id < wbase+j  <=>  d < j
        c0 += (d < 0); c1 += (d < 1); c2 += (d < 2); c3 += (d < 3); c4 += (d < 4);
    }
    int msum = m0.x + m0.y + m0.z + m0.w + m1.x + m1.y + m1.z + m1.w;

    // pack: p0 = c0|c1|c2, p1 = c3|c4|msum  (10 bits each, sums <= 512)
    int p0 = c0 | (c1 << 10) | (c2 << 20);
    int p1 = c3 | (c4 << 10) | (msum << 20);
    #pragma unroll
    for (int sft = 16; sft > 0; sft >>= 1) {
        p0 += __shfl_down_sync(0xffffffffu, p0, sft);
        p1 += __shfl_down_sync(0xffffffffu, p1, sft);
    }
    if ((t & 31) == 0) { sred[t >> 5] = p0; sred[2 + (t >> 5)] = p1; }
    if (t == 63) smeta[1] = ids[7] + 1;   // wordnum (sorted -> last is max)
    __syncthreads();

    if (t == 0) {
        int q0 = sred[0] + sred[1];
        int q1 = sred[2] + sred[3];
        scut[0] = q0 & 1023;
        scut[1] = (q0 >> 10) & 1023;
        scut[2] = (q0 >> 20) & 1023;
        scut[3] = q1 & 1023;
        scut[4] = (q1 >> 10) & 1023;
        smeta[0] = (q1 >> 20) - 1;        // hi = 1 + (sum(mask) - 2)
    }
    __syncthreads();

    int hi = smeta[0];
    int wordnum = smeta[1];
    const int stride4 = BATCH * DDIM / 4;

    // --- pool the 4 words ---
    #pragma unroll
    for (int j = 0; j < WPB; ++j) {
        int s = scut[j];
        int e = scut[j + 1];
        s = s > 1 ? s : 1;
        e = e < hi ? e : hi;
        int n = e - s;

        const float4* p = reinterpret_cast<const float4*>(cf)
                        + (long long)s * stride4 + b * (DDIM / 4) + t;
        float4 acc = pool_body(p, stride4, n);

        float inv = 1.0f / (float)(n > 0 ? n : 1);
        acc.x *= inv; acc.y *= inv; acc.z *= inv; acc.w *= inv;

        int w = wbase + j;
        float4* o = reinterpret_cast<float4*>(out)
                  + (long long)(w * BATCH + b) * (DDIM / 4) + t;
        __stcs(o, acc);

        if (t == 0 && mask_out != nullptr) {
            __stcs(&mask_out[w * BATCH + b], (w < wordnum) ? 1.0f : 0.0f);
        }
    }
}

extern "C" void kernel_launch(void* const* d_in, const int* in_sizes, int n_in,
                              void* d_out, int out_size) {
    const float* char_feats = (const float*)d_in[0];
    const int*   word_ids   = (const int*)d_in[1];
    const int*   amask      = (const int*)d_in[2];
    float* out = (float*)d_out;

    const int feats_elems = NW * BATCH * DDIM;
    float* mask_out = (out_size > feats_elems) ? (out + feats_elems) : nullptr;

    fused_kernel<<<(NW / WPB) * BATCH, 64>>>(char_feats, word_ids, amask, out, mask_out);
}

// round 11
// speedup vs baseline: 1.1182x; 1.1182x over previous
#include <cuda_runtime.h>
#include <cuda_bf16.h>

// char_feats: [L=512, B=256, D=256] f32 (time-major)
// word_ids:   [B, L] i32 (per-row non-decreasing, dense 0..n-1, < 128)
// attention_mask: [B, L] i32
// out: word_feats [W=128, B, D] f32 (+ masks [W, B] f32 if out_size allows)
#define LSEQ 512
#define NW   128
#define BATCH 256
#define DDIM  256
#define WPB   4            // words per block (one 64-thread group each)
#define NTHREADS (64 * WPB)

__device__ __forceinline__ int clampw(int v) {
    return v < 0 ? 0 : (v > NW - 1 ? NW - 1 : v);
}

// 4/2/1 ladder; single accumulator; evict-first streaming loads.
__device__ __forceinline__ float4 pool_body(const float4* p, int stride4, int n) {
    float4 acc = make_float4(0.f, 0.f, 0.f, 0.f);
    int rem = n;
    while (rem >= 4) {
        float4 v0 = __ldcs(p);
        float4 v1 = __ldcs(p + stride4);
        float4 v2 = __ldcs(p + 2 * stride4);
        float4 v3 = __ldcs(p + 3 * stride4);
        acc.x += v0.x; acc.y += v0.y; acc.z += v0.z; acc.w += v0.w;
        acc.x += v1.x; acc.y += v1.y; acc.z += v1.z; acc.w += v1.w;
        acc.x += v2.x; acc.y += v2.y; acc.z += v2.z; acc.w += v2.w;
        acc.x += v3.x; acc.y += v3.y; acc.z += v3.z; acc.w += v3.w;
        p += 4 * stride4;
        rem -= 4;
    }
    if (rem >= 2) {
        float4 v0 = __ldcs(p);
        float4 v1 = __ldcs(p + stride4);
        acc.x += v0.x; acc.y += v0.y; acc.z += v0.z; acc.w += v0.w;
        acc.x += v1.x; acc.y += v1.y; acc.z += v1.z; acc.w += v1.w;
        p += 2 * stride4;
        rem -= 2;
    }
    if (rem >= 1) {
        float4 v0 = __ldcs(p);
        acc.x += v0.x; acc.y += v0.y; acc.z += v0.z; acc.w += v0.w;
    }
    return acc;
}

// One 256-thread block per (4 words, batch); b fast axis. Metadata row loaded
// once (int2/thread), reduced once to 5 cut points; then 4 warp-pairs pool
// their words CONCURRENTLY (no serialization, no grid shrink).
__global__ void __launch_bounds__(NTHREADS, 8)
fused_kernel(const float* __restrict__ cf,
             const int* __restrict__ word_ids,
             const int* __restrict__ amask,
             float* __restrict__ out,
             float* __restrict__ mask_out) {
    int lid = blockIdx.x;
    int b = lid & (BATCH - 1);        // fast axis
    int wbase = (lid >> 8) * WPB;     // slow axis: words wbase..wbase+3
    int t = threadIdx.x;              // 0..255

    __shared__ int sred[16];          // 8 warps x 2 packed partials
    __shared__ int scut[WPB + 1];
    __shared__ int smeta[2];          // hi, wordnum

    // --- metadata: each thread loads 2 ids + 2 mask (int2) ---
    const int2* wp = reinterpret_cast<const int2*>(word_ids + b * LSEQ);
    int2 wv = __ldg(wp + t);
    const int2* mp = reinterpret_cast<const int2*>(amask + b * LSEQ);
    int2 mv = __ldg(mp + t);

    int i0 = clampw(wv.x), i1 = clampw(wv.y);

    int c0 = (i0 < wbase)     + (i1 < wbase);
    int c1 = (i0 < wbase + 1) + (i1 < wbase + 1);
    int c2 = (i0 < wbase + 2) + (i1 < wbase + 2);
    int c3 = (i0 < wbase + 3) + (i1 < wbase + 3);
    int c4 = (i0 < wbase + 4) + (i1 < wbase + 4);
    int msum = mv.x + mv.y;

    // pack: p0 = c0|c1|c2, p1 = c3|c4|msum (10-bit fields, block sums <= 512)
    int p0 = c0 | (c1 << 10) | (c2 << 20);
    int p1 = c3 | (c4 << 10) | (msum << 20);
    #pragma unroll
    for (int sft = 16; sft > 0; sft >>= 1) {
        p0 += __shfl_down_sync(0xffffffffu, p0, sft);
        p1 += __shfl_down_sync(0xffffffffu, p1, sft);
    }
    int warp = t >> 5;
    if ((t & 31) == 0) { sred[warp] = p0; sred[8 + warp] = p1; }
    if (t == NTHREADS - 1) smeta[1] = i1 + 1;  // wordnum (sorted -> last is max)
    __syncthreads();

    if (t == 0) {
        int q0 = 0, q1 = 0;
        #pragma unroll
        for (int i = 0; i < 8; ++i) { q0 += sred[i]; q1 += sred[8 + i]; }
        scut[0] = q0 & 1023;
        scut[1] = (q0 >> 10) & 1023;
        scut[2] = (q0 >> 20) & 1023;
        scut[3] = q1 & 1023;
        scut[4] = (q1 >> 10) & 1023;
        smeta[0] = (q1 >> 20) - 1;             // hi = 1 + (sum(mask) - 2)
    }
    __syncthreads();

    // --- pooling: group g (64 threads) handles word wbase+g ---
    int g  = t >> 6;                  // 0..3
    int gt = t & 63;                  // lane within group

    int hi = smeta[0];
    int wordnum = smeta[1];
    int s = scut[g];
    int e = scut[g + 1];
    s = s > 1 ? s : 1;
    e = e < hi ? e : hi;
    int n = e - s;                    // may be <= 0 (empty / padded word)

    const int stride4 = BATCH * DDIM / 4;
    const float4* p = reinterpret_cast<const float4*>(cf)
                    + (long long)s * stride4 + b * (DDIM / 4) + gt;

    float4 acc = pool_body(p, stride4, n);

    float inv = 1.0f / (float)(n > 0 ? n : 1);
    acc.x *= inv; acc.y *= inv; acc.z *= inv; acc.w *= inv;

    int w = wbase + g;
    float4* o = reinterpret_cast<float4*>(out)
              + (long long)(w * BATCH + b) * (DDIM / 4) + gt;
    __stcs(o, acc);

    if (gt == 0 && mask_out != nullptr) {
        __stcs(&mask_out[w * BATCH + b], (w < wordnum) ? 1.0f : 0.0f);
    }
}

extern "C" void kernel_launch(void* const* d_in, const int* in_sizes, int n_in,
                              void* d_out, int out_size) {
    const float* char_feats = (const float*)d_in[0];
    const int*   word_ids   = (const int*)d_in[1];
    const int*   amask      = (const int*)d_in[2];
    float* out = (float*)d_out;

    const int feats_elems = NW * BATCH * DDIM;
    float* mask_out = (out_size > feats_elems) ? (out + feats_elems) : nullptr;

    fused_kernel<<<(NW / WPB) * BATCH, NTHREADS>>>(char_feats, word_ids, amask,
                                                   out, mask_out);
}